// round 5
// baseline (speedup 1.0000x reference)
#include <cuda_runtime.h>

#define Bn 128
#define Ln 1024
#define INF_ 136
#define F1 256
#define F2 512
#define Hn 256
#define G4 1024
#define HPITCH 260

// ---- scratch (device globals) ----
__device__ float g_W1T[INF_ * F1];
__device__ float g_W2T[F1 * F2];
__device__ float g_W4_0[(size_t)F2 * G4];   // packed [k][256][4]
__device__ float g_W4_1[(size_t)Hn * G4];
__device__ float g_W4_2[(size_t)Hn * G4];
__device__ float g_bsum0[G4];
__device__ float g_bsum1[G4];
__device__ float g_bsum2[G4];
__device__ float g_feat[(size_t)Ln * Bn * F2];   // [t][b][512]
__device__ float g_xg[(size_t)Ln * Bn * G4];     // [t*B+b][1024]
__device__ float g_hA[(size_t)Ln * Bn * Hn];
__device__ float g_hB[(size_t)Ln * Bn * Hn];
__device__ float g_hstate[2][Bn * Hn];           // [b][u] ping-pong
__device__ unsigned g_grpctr[4 * 32];            // 4 counters, 128B apart

// ---- f32x2 packed FMA ----
union F2U { float2 f; unsigned long long u; };
__device__ __forceinline__ float2 ffma2(float2 a, float2 b, float2 c) {
    F2U A, B, C, D;
    A.f = a; B.f = b; C.f = c;
    asm("fma.rn.f32x2 %0, %1, %2, %3;" : "=l"(D.u) : "l"(A.u), "l"(B.u), "l"(C.u));
    return D.f;
}

__device__ __forceinline__ float fast_sigmoid(float x) {
    return 1.f / (1.f + __expf(-x));
}
__device__ __forceinline__ float fast_tanh(float x) {
    return 2.f / (1.f + __expf(-2.f * x)) - 1.f;
}

// ---- fused prep: transposes + packs + bias sums in one kernel ----
#define N1 (INF_ * F1)
#define N2 (F1 * F2)
#define N3 (F2 * G4)
#define N4 (Hn * G4)
__global__ void prep_kernel(const float* __restrict__ W1, const float* __restrict__ W2,
                            const float* __restrict__ w_ih0, const float* __restrict__ w_ih1,
                            const float* __restrict__ w_ih2,
                            const float* __restrict__ b_ih0, const float* __restrict__ b_hh0,
                            const float* __restrict__ b_ih1, const float* __restrict__ b_hh1,
                            const float* __restrict__ b_ih2, const float* __restrict__ b_hh2) {
    int i = blockIdx.x * blockDim.x + threadIdx.x;
    if (i < N1) {
        int r = i / INF_, c = i % INF_;
        g_W1T[c * F1 + r] = W1[i];
        return;
    }
    i -= N1;
    if (i < N2) {
        int r = i / F1, c = i % F1;
        g_W2T[c * F2 + r] = W2[i];
        return;
    }
    i -= N2;
    if (i < N3) {
        int k = i >> 10, rem = i & 1023, c = rem >> 2, g = rem & 3;
        g_W4_0[i] = w_ih0[(size_t)(g * 256 + c) * F2 + k];
        return;
    }
    i -= N3;
    if (i < N4) {
        int k = i >> 10, rem = i & 1023, c = rem >> 2, g = rem & 3;
        g_W4_1[i] = w_ih1[(size_t)(g * 256 + c) * Hn + k];
        return;
    }
    i -= N4;
    if (i < N4) {
        int k = i >> 10, rem = i & 1023, c = rem >> 2, g = rem & 3;
        g_W4_2[i] = w_ih2[(size_t)(g * 256 + c) * Hn + k];
        return;
    }
    i -= N4;
    if (i < G4) { g_bsum0[i] = b_ih0[i] + b_hh0[i]; return; }
    i -= G4;
    if (i < G4) { g_bsum1[i] = b_ih1[i] + b_hh1[i]; return; }
    i -= G4;
    if (i < G4) { g_bsum2[i] = b_ih2[i] + b_hh2[i]; return; }
}
#define PREP_TOTAL (N1 + N2 + N3 + 2 * N4 + 3 * G4)

__global__ void reset_kernel() {
    int i = blockIdx.x * blockDim.x + threadIdx.x;
    if (i < 128) g_grpctr[i] = 0u;
}

// ---- MLP v2 (ffma2, k-major smem): feat = relu(relu(x@W1^T+b1)@W2^T+b2) ----
#define H1P 18
__global__ __launch_bounds__(256) void mlp2_kernel(const float* __restrict__ x,
                                                   const float* __restrict__ b1,
                                                   const float* __restrict__ b2) {
    __shared__ float xs[INF_ * 16];      // [k][16 rows]
    __shared__ float h1s[F1 * H1P];      // [k][16 rows + pad]
    const int tid = threadIdx.x;
    const size_t row0 = (size_t)blockIdx.x * 16;

    const float* xr = x + row0 * INF_;
    for (int idx = tid; idx < 16 * INF_; idx += 256) {
        int r = idx / INF_, k = idx % INF_;
        xs[k * 16 + r] = xr[idx];
    }
    __syncthreads();

    {   // layer 1: col = tid, rows packed in pairs
        float2 acc[8];
        const float bb = b1[tid];
#pragma unroll
        for (int p = 0; p < 8; ++p) acc[p] = make_float2(bb, bb);
#pragma unroll 2
        for (int k = 0; k < INF_; ++k) {
            float w = g_W1T[k * F1 + tid];
            float2 w2 = make_float2(w, w);
            const float4* xp = (const float4*)(xs + k * 16);
#pragma unroll
            for (int q = 0; q < 4; ++q) {
                float4 v = xp[q];
                acc[2 * q]     = ffma2(make_float2(v.x, v.y), w2, acc[2 * q]);
                acc[2 * q + 1] = ffma2(make_float2(v.z, v.w), w2, acc[2 * q + 1]);
            }
        }
        float* hp = h1s + tid * H1P;
#pragma unroll
        for (int p = 0; p < 8; ++p) {
            *(float2*)(hp + 2 * p) = make_float2(fmaxf(acc[p].x, 0.f), fmaxf(acc[p].y, 0.f));
        }
    }
    __syncthreads();

    {   // layer 2: cols tid, tid+256
        float2 acc0[8], acc1[8];
        const float bb0 = b2[tid], bb1 = b2[tid + 256];
#pragma unroll
        for (int p = 0; p < 8; ++p) { acc0[p] = make_float2(bb0, bb0); acc1[p] = make_float2(bb1, bb1); }
#pragma unroll 2
        for (int k = 0; k < F1; ++k) {
            float w0 = g_W2T[k * F2 + tid];
            float w1 = g_W2T[k * F2 + tid + 256];
            float2 w20 = make_float2(w0, w0);
            float2 w21 = make_float2(w1, w1);
            const float* hp = h1s + k * H1P;
#pragma unroll
            for (int p = 0; p < 8; ++p) {
                float2 a = *(const float2*)(hp + 2 * p);
                acc0[p] = ffma2(a, w20, acc0[p]);
                acc1[p] = ffma2(a, w21, acc1[p]);
            }
        }
#pragma unroll
        for (int p = 0; p < 8; ++p) {
#pragma unroll
            for (int h = 0; h < 2; ++h) {
                size_t row = row0 + 2 * p + h;
                int b_ = (int)(row / Ln), t_ = (int)(row % Ln);
                float* fp = g_feat + ((size_t)t_ * Bn + b_) * F2;
                float v0 = h ? acc0[p].y : acc0[p].x;
                float v1 = h ? acc1[p].y : acc1[p].x;
                fp[tid] = fmaxf(v0, 0.f);
                fp[tid + 256] = fmaxf(v1, 0.f);
            }
        }
    }
}

// ---- xg GEMM (unchanged) ----
template <int K, bool SRC_KMAJOR>
__global__ __launch_bounds__(256, 1) void xg2_kernel(const float* __restrict__ A,
                                                     const float* __restrict__ W4,
                                                     const float* __restrict__ bsum,
                                                     float* __restrict__ out) {
    extern __shared__ float As[];  // [K][36]
    const int tid = threadIdx.x;
    const int row0 = blockIdx.x * 32;

    if (SRC_KMAJOR) {
        const int t = row0 >> 7, b0 = row0 & 127;
        const float* base = A + ((size_t)t * K) * 128 + b0;
        for (int i = tid; i < K * 8; i += 256) {
            int k = i >> 3, r4 = (i & 7) * 4;
            *(float4*)(As + k * 36 + r4) = *(const float4*)(base + (size_t)k * 128 + r4);
        }
    } else {
        constexpr int KQ = K / 4;
        for (int i = tid; i < 32 * KQ; i += 256) {
            int r = i / KQ, kq = i % KQ;
            float4 v = *(const float4*)(A + (size_t)(row0 + r) * K + kq * 4);
            As[(kq * 4 + 0) * 36 + r] = v.x;
            As[(kq * 4 + 1) * 36 + r] = v.y;
            As[(kq * 4 + 2) * 36 + r] = v.z;
            As[(kq * 4 + 3) * 36 + r] = v.w;
        }
    }
    __syncthreads();

    float2 acc[16][4];
#pragma unroll
    for (int p = 0; p < 16; ++p)
#pragma unroll
        for (int g = 0; g < 4; ++g) acc[p][g] = make_float2(0.f, 0.f);

    const float4* wp = (const float4*)W4 + tid;
#pragma unroll 2
    for (int k = 0; k < K; ++k) {
        float4 w4 = wp[(size_t)k * 256];
        float2 w2[4];
        w2[0] = make_float2(w4.x, w4.x);
        w2[1] = make_float2(w4.y, w4.y);
        w2[2] = make_float2(w4.z, w4.z);
        w2[3] = make_float2(w4.w, w4.w);
        const float4* ap = (const float4*)(As + k * 36);
#pragma unroll
        for (int q = 0; q < 8; ++q) {
            float4 a4 = ap[q];
            float2 alo = make_float2(a4.x, a4.y);
            float2 ahi = make_float2(a4.z, a4.w);
#pragma unroll
            for (int g = 0; g < 4; ++g) {
                acc[2 * q][g]     = ffma2(alo, w2[g], acc[2 * q][g]);
                acc[2 * q + 1][g] = ffma2(ahi, w2[g], acc[2 * q + 1][g]);
            }
        }
    }

    float bb[4];
#pragma unroll
    for (int g = 0; g < 4; ++g) bb[g] = bsum[tid + g * 256];
#pragma unroll
    for (int p = 0; p < 16; ++p) {
        float* o0 = out + (size_t)(row0 + 2 * p) * G4 + tid;
        float* o1 = o0 + G4;
#pragma unroll
        for (int g = 0; g < 4; ++g) {
            o0[g * 256] = acc[p][g].x + bb[g];
            o1[g * 256] = acc[p][g].y + bb[g];
        }
    }
}

// ---- LSTM recurrence v4: broadcast-h / distinct-w tiling (crossbar-minimal) ----
// Block: 32 rows x 32 gate-cols. Warp w: rows 4w..4w+3, all 32 cols (lane = col).
template <bool OUT_TBU>
__global__ __launch_bounds__(256) void lstm4_kernel(const float* __restrict__ xg,
                                                    const float* __restrict__ w_hh,
                                                    float* __restrict__ hout) {
    extern __shared__ float sm[];
    float* w_s = sm;                          // [32 cols][HPITCH]
    float* h_s = sm + 32 * HPITCH;            // [32 rows][HPITCH]
    float* gx  = sm + 64 * HPITCH;            // [32 cols][36 rows]

    const int tid = threadIdx.x;
    const int bid = blockIdx.x;
    const int ubase = (bid & 31) * 8;
    const int rbase = (bid >> 5) * 32;
    const int grp = bid >> 5;

    const int w = tid >> 5;
    const int lane = tid & 31;
    const int c = lane;                                 // block-local gate col
    const int jcol = (c >> 3) * Hn + ubase + (c & 7);   // global gate col
    const int r0 = 4 * w;                               // warp's first row

    // stage w_hh [col][k] k-contiguous; zero h_s (t=0 uses zeros)
    for (int j = 0; j < 32; ++j) {
        int jc = (j >> 3) * Hn + ubase + (j & 7);
        w_s[j * HPITCH + tid] = w_hh[(size_t)jc * Hn + tid];
    }
    for (int i = tid; i < 32 * HPITCH; i += 256) h_s[i] = 0.f;

    const int prow = tid >> 3;   // pointwise row 0..31
    const int puni = tid & 7;    // pointwise unit 0..7
    float cst = 0.f;
    unsigned* ctr = &g_grpctr[grp * 32];

    // first-step xg prefetch: lane handles rows r0..r0+3, col jcol
    const float* xb = xg + ((size_t)rbase + r0) * G4 + jcol;
    float x0 = xb[0];
    float x1 = xb[G4];
    float x2 = xb[2 * G4];
    float x3 = xb[3 * G4];

    __syncthreads();

    for (int t = 0; t < Ln; ++t) {
        if (t > 0) {
            const float* hrd = g_hstate[t & 1];
            for (int i = tid; i < 2048; i += 256) {    // 32 rows x 64 float4
                int r = i >> 6, q = (i & 63) * 4;
                *(float4*)(h_s + r * HPITCH + q) = *(const float4*)(hrd + (size_t)(rbase + r) * Hn + q);
            }
        }
        __syncthreads();

        float2 a01 = make_float2(0.f, 0.f);
        float2 a23 = make_float2(0.f, 0.f);
        const float* h0p = h_s + (r0 + 0) * HPITCH;
        const float* h1p = h_s + (r0 + 1) * HPITCH;
        const float* h2p = h_s + (r0 + 2) * HPITCH;
        const float* h3p = h_s + (r0 + 3) * HPITCH;
        const float* wp = w_s + c * HPITCH;
#pragma unroll 4
        for (int k = 0; k < Hn; k += 4) {
            float4 wv = *(const float4*)(wp + k);
            float4 h0 = *(const float4*)(h0p + k);   // full-warp broadcast
            float4 h1 = *(const float4*)(h1p + k);
            float4 h2 = *(const float4*)(h2p + k);
            float4 h3 = *(const float4*)(h3p + k);
            a01 = ffma2(make_float2(h0.x, h1.x), make_float2(wv.x, wv.x), a01);
            a23 = ffma2(make_float2(h2.x, h3.x), make_float2(wv.x, wv.x), a23);
            a01 = ffma2(make_float2(h0.y, h1.y), make_float2(wv.y, wv.y), a01);
            a23 = ffma2(make_float2(h2.y, h3.y), make_float2(wv.y, wv.y), a23);
            a01 = ffma2(make_float2(h0.z, h1.z), make_float2(wv.z, wv.z), a01);
            a23 = ffma2(make_float2(h2.z, h3.z), make_float2(wv.z, wv.z), a23);
            a01 = ffma2(make_float2(h0.w, h1.w), make_float2(wv.w, wv.w), a01);
            a23 = ffma2(make_float2(h2.w, h3.w), make_float2(wv.w, wv.w), a23);
        }
        a01.x += x0; a01.y += x1; a23.x += x2; a23.y += x3;
        *(float4*)(gx + c * 36 + r0) = make_float4(a01.x, a01.y, a23.x, a23.y);
        __syncthreads();

        // pointwise: thread owns (row prow, unit puni)
        float iv = gx[(0 * 8 + puni) * 36 + prow];
        float fv = gx[(1 * 8 + puni) * 36 + prow];
        float gv = gx[(2 * 8 + puni) * 36 + prow];
        float ov = gx[(3 * 8 + puni) * 36 + prow];
        iv = fast_sigmoid(iv);
        fv = fast_sigmoid(fv);
        gv = fast_tanh(gv);
        ov = fast_sigmoid(ov);
        cst = fv * cst + iv * gv;
        float hv = ov * fast_tanh(cst);
        float* hwr = g_hstate[(t + 1) & 1];
        hwr[(size_t)(rbase + prow) * Hn + ubase + puni] = hv;
        if (OUT_TBU)
            hout[((size_t)t * Bn + rbase + prow) * Hn + ubase + puni] = hv;
        else
            hout[((size_t)t * Hn + ubase + puni) * Bn + rbase + prow] = hv;

        // prefetch next-step xg (independent of barrier)
        if (t + 1 < Ln) {
            const float* xp = xg + (((size_t)(t + 1)) * Bn + rbase + r0) * G4 + jcol;
            x0 = xp[0];
            x1 = xp[G4];
            x2 = xp[2 * G4];
            x3 = xp[3 * G4];
        }

        __syncthreads();
        if (tid == 0) {
            asm volatile("red.release.gpu.global.add.u32 [%0], %1;" :: "l"(ctr), "r"(1u) : "memory");
            const unsigned target = (unsigned)(t + 1) * 32u;
            unsigned v;
            do {
                asm volatile("ld.acquire.gpu.global.u32 %0, [%1];" : "=r"(v) : "l"(ctr) : "memory");
            } while (v < target);
        }
        __syncthreads();
    }
}

// ---- decision head + ragged mean (hseq is [t][b][u]) ----
__global__ __launch_bounds__(256) void decision_kernel(const float* __restrict__ hseq,
                                                       const float* __restrict__ Wd,
                                                       const float* __restrict__ bd,
                                                       const int* __restrict__ length,
                                                       float* __restrict__ out) {
    const int b = blockIdx.x;
    const int tid = threadIdx.x;
    const int len = length[b];
    const float w = Wd[tid];
    float s0 = 0.f, s1 = 0.f, s2 = 0.f, s3 = 0.f;
    int t = 0;
    for (; t + 4 <= len; t += 4) {
        s0 = fmaf(hseq[((size_t)(t + 0) * Bn + b) * Hn + tid], w, s0);
        s1 = fmaf(hseq[((size_t)(t + 1) * Bn + b) * Hn + tid], w, s1);
        s2 = fmaf(hseq[((size_t)(t + 2) * Bn + b) * Hn + tid], w, s2);
        s3 = fmaf(hseq[((size_t)(t + 3) * Bn + b) * Hn + tid], w, s3);
    }
    for (; t < len; ++t) s0 = fmaf(hseq[((size_t)t * Bn + b) * Hn + tid], w, s0);
    float s = (s0 + s1) + (s2 + s3);
    __shared__ float red[256];
    red[tid] = s;
    __syncthreads();
    for (int st = 128; st > 0; st >>= 1) {
        if (tid < st) red[tid] += red[tid + st];
        __syncthreads();
    }
    if (tid == 0) out[b] = red[0] / (float)len + bd[0];
}

extern "C" void kernel_launch(void* const* d_in, const int* in_sizes, int n_in,
                              void* d_out, int out_size) {
    const float* x     = (const float*)d_in[0];
    const int* length  = (const int*)d_in[1];
    const float* W1    = (const float*)d_in[2];
    const float* b1    = (const float*)d_in[3];
    const float* W2    = (const float*)d_in[4];
    const float* b2    = (const float*)d_in[5];
    const float* w_ih0 = (const float*)d_in[6];
    const float* w_hh0 = (const float*)d_in[7];
    const float* b_ih0 = (const float*)d_in[8];
    const float* b_hh0 = (const float*)d_in[9];
    const float* w_ih1 = (const float*)d_in[10];
    const float* w_hh1 = (const float*)d_in[11];
    const float* b_ih1 = (const float*)d_in[12];
    const float* b_hh1 = (const float*)d_in[13];
    const float* w_ih2 = (const float*)d_in[14];
    const float* w_hh2 = (const float*)d_in[15];
    const float* b_ih2 = (const float*)d_in[16];
    const float* b_hh2 = (const float*)d_in[17];
    const float* Wd    = (const float*)d_in[18];
    const float* bd    = (const float*)d_in[19];
    float* out = (float*)d_out;

    float *dP0, *dP1, *dP2, *dB0, *dB1, *dB2, *dFeat, *dXg, *dHA, *dHB;
    cudaGetSymbolAddress((void**)&dP0, g_W4_0);
    cudaGetSymbolAddress((void**)&dP1, g_W4_1);
    cudaGetSymbolAddress((void**)&dP2, g_W4_2);
    cudaGetSymbolAddress((void**)&dB0, g_bsum0);
    cudaGetSymbolAddress((void**)&dB1, g_bsum1);
    cudaGetSymbolAddress((void**)&dB2, g_bsum2);
    cudaGetSymbolAddress((void**)&dFeat, g_feat);
    cudaGetSymbolAddress((void**)&dXg, g_xg);
    cudaGetSymbolAddress((void**)&dHA, g_hA);
    cudaGetSymbolAddress((void**)&dHB, g_hB);

    const int xg_smem512 = 512 * 36 * sizeof(float);
    const int xg_smem256 = 256 * 36 * sizeof(float);
    const int lstm_smem = (64 * HPITCH + 32 * 36) * sizeof(float);
    cudaFuncSetAttribute(xg2_kernel<F2, false>, cudaFuncAttributeMaxDynamicSharedMemorySize, xg_smem512);
    cudaFuncSetAttribute(xg2_kernel<Hn, true>, cudaFuncAttributeMaxDynamicSharedMemorySize, xg_smem256);
    cudaFuncSetAttribute(lstm4_kernel<false>, cudaFuncAttributeMaxDynamicSharedMemorySize, lstm_smem);
    cudaFuncSetAttribute(lstm4_kernel<true>, cudaFuncAttributeMaxDynamicSharedMemorySize, lstm_smem);

    prep_kernel<<<(PREP_TOTAL + 255) / 256, 256>>>(W1, W2, w_ih0, w_ih1, w_ih2,
                                                   b_ih0, b_hh0, b_ih1, b_hh1, b_ih2, b_hh2);

    const int nrows = Bn * Ln;
    mlp2_kernel<<<nrows / 16, 256>>>(x, b1, b2);

    // layer 0
    xg2_kernel<F2, false><<<nrows / 32, 256, xg_smem512>>>(dFeat, dP0, dB0, dXg);
    reset_kernel<<<1, 256>>>();
    lstm4_kernel<false><<<128, 256, lstm_smem>>>(dXg, w_hh0, dHA);
    // layer 1
    xg2_kernel<Hn, true><<<nrows / 32, 256, xg_smem256>>>(dHA, dP1, dB1, dXg);
    reset_kernel<<<1, 256>>>();
    lstm4_kernel<false><<<128, 256, lstm_smem>>>(dXg, w_hh1, dHB);
    // layer 2
    xg2_kernel<Hn, true><<<nrows / 32, 256, xg_smem256>>>(dHB, dP2, dB2, dXg);
    reset_kernel<<<1, 256>>>();
    lstm4_kernel<true><<<128, 256, lstm_smem>>>(dXg, w_hh2, dHA);

    decision_kernel<<<Bn, 256>>>(dHA, Wd, bd, length, out);
}

// round 7
// speedup vs baseline: 1.1310x; 1.1310x over previous
#include <cuda_runtime.h>

#define Bn 128
#define Ln 1024
#define INF_ 136
#define F1 256
#define F2 512
#define Hn 256
#define G4 1024
#define WPITCH 260

// ---- scratch (device globals) ----
__device__ float g_W1T[INF_ * F1];
__device__ float g_W2T[F1 * F2];
__device__ float g_W4_0[(size_t)F2 * G4];   // packed [k][256][4]
__device__ float g_W4_1[(size_t)Hn * G4];
__device__ float g_W4_2[(size_t)Hn * G4];
__device__ float g_bsum0[G4];
__device__ float g_bsum1[G4];
__device__ float g_bsum2[G4];
__device__ float g_feat[(size_t)Ln * Bn * F2];   // [t][b][512]
__device__ float g_xg[(size_t)Ln * Bn * G4];     // [t*B+b][1024]
__device__ float g_hA[(size_t)Ln * Bn * Hn];
__device__ float g_hB[(size_t)Ln * Bn * Hn];
__device__ float g_hstate[3][2][Hn * Bn];        // per-layer [u][b] ping-pong
__device__ unsigned g_grpctr[3][4 * 32];         // per-layer group counters

// ---- f32x2 packed FMA ----
union F2U { float2 f; unsigned long long u; };
__device__ __forceinline__ float2 ffma2(float2 a, float2 b, float2 c) {
    F2U A, B, C, D;
    A.f = a; B.f = b; C.f = c;
    asm("fma.rn.f32x2 %0, %1, %2, %3;" : "=l"(D.u) : "l"(A.u), "l"(B.u), "l"(C.u));
    return D.f;
}

__device__ __forceinline__ float fast_sigmoid(float x) {
    return 1.f / (1.f + __expf(-x));
}
__device__ __forceinline__ float fast_tanh(float x) {
    return 2.f / (1.f + __expf(-2.f * x)) - 1.f;
}

// ---- fused prep: transposes + packs + bias sums + state/counter zeroing ----
#define N1 (INF_ * F1)
#define N2 (F1 * F2)
#define N3 (F2 * G4)
#define N4 (Hn * G4)
__global__ void prep_kernel(const float* __restrict__ W1, const float* __restrict__ W2,
                            const float* __restrict__ w_ih0, const float* __restrict__ w_ih1,
                            const float* __restrict__ w_ih2,
                            const float* __restrict__ b_ih0, const float* __restrict__ b_hh0,
                            const float* __restrict__ b_ih1, const float* __restrict__ b_hh1,
                            const float* __restrict__ b_ih2, const float* __restrict__ b_hh2) {
    int i = blockIdx.x * blockDim.x + threadIdx.x;
    if (i < N1) {
        int r = i / INF_, c = i % INF_;
        g_W1T[c * F1 + r] = W1[i];
        return;
    }
    i -= N1;
    if (i < N2) {
        int r = i / F1, c = i % F1;
        g_W2T[c * F2 + r] = W2[i];
        return;
    }
    i -= N2;
    if (i < N3) {
        int k = i >> 10, rem = i & 1023, c = rem >> 2, g = rem & 3;
        g_W4_0[i] = w_ih0[(size_t)(g * 256 + c) * F2 + k];
        return;
    }
    i -= N3;
    if (i < N4) {
        int k = i >> 10, rem = i & 1023, c = rem >> 2, g = rem & 3;
        g_W4_1[i] = w_ih1[(size_t)(g * 256 + c) * Hn + k];
        return;
    }
    i -= N4;
    if (i < N4) {
        int k = i >> 10, rem = i & 1023, c = rem >> 2, g = rem & 3;
        g_W4_2[i] = w_ih2[(size_t)(g * 256 + c) * Hn + k];
        return;
    }
    i -= N4;
    if (i < G4) { g_bsum0[i] = b_ih0[i] + b_hh0[i]; return; }
    i -= G4;
    if (i < G4) { g_bsum1[i] = b_ih1[i] + b_hh1[i]; return; }
    i -= G4;
    if (i < G4) { g_bsum2[i] = b_ih2[i] + b_hh2[i]; return; }
    i -= G4;
    if (i < 3 * 128) { (&g_grpctr[0][0])[i] = 0u; return; }
    i -= 3 * 128;
    // zero each layer's initial (slot 0) read buffer
    if (i < 3 * Hn * Bn) {
        int layer = i / (Hn * Bn);
        g_hstate[layer][0][i % (Hn * Bn)] = 0.f;
        return;
    }
}
#define PREP_TOTAL (N1 + N2 + N3 + 2 * N4 + 3 * G4 + 3 * 128 + 3 * Hn * Bn)

// ---- MLP v2 (ffma2, k-major smem) ----
#define H1P 18
__global__ __launch_bounds__(256) void mlp2_kernel(const float* __restrict__ x,
                                                   const float* __restrict__ b1,
                                                   const float* __restrict__ b2) {
    __shared__ float xs[INF_ * 16];
    __shared__ float h1s[F1 * H1P];
    const int tid = threadIdx.x;
    const size_t row0 = (size_t)blockIdx.x * 16;

    const float* xr = x + row0 * INF_;
    for (int idx = tid; idx < 16 * INF_; idx += 256) {
        int r = idx / INF_, k = idx % INF_;
        xs[k * 16 + r] = xr[idx];
    }
    __syncthreads();

    {
        float2 acc[8];
        const float bb = b1[tid];
#pragma unroll
        for (int p = 0; p < 8; ++p) acc[p] = make_float2(bb, bb);
#pragma unroll 2
        for (int k = 0; k < INF_; ++k) {
            float w = g_W1T[k * F1 + tid];
            float2 w2 = make_float2(w, w);
            const float4* xp = (const float4*)(xs + k * 16);
#pragma unroll
            for (int q = 0; q < 4; ++q) {
                float4 v = xp[q];
                acc[2 * q]     = ffma2(make_float2(v.x, v.y), w2, acc[2 * q]);
                acc[2 * q + 1] = ffma2(make_float2(v.z, v.w), w2, acc[2 * q + 1]);
            }
        }
        float* hp = h1s + tid * H1P;
#pragma unroll
        for (int p = 0; p < 8; ++p) {
            *(float2*)(hp + 2 * p) = make_float2(fmaxf(acc[p].x, 0.f), fmaxf(acc[p].y, 0.f));
        }
    }
    __syncthreads();

    {
        float2 acc0[8], acc1[8];
        const float bb0 = b2[tid], bb1 = b2[tid + 256];
#pragma unroll
        for (int p = 0; p < 8; ++p) { acc0[p] = make_float2(bb0, bb0); acc1[p] = make_float2(bb1, bb1); }
#pragma unroll 2
        for (int k = 0; k < F1; ++k) {
            float w0 = g_W2T[k * F2 + tid];
            float w1 = g_W2T[k * F2 + tid + 256];
            float2 w20 = make_float2(w0, w0);
            float2 w21 = make_float2(w1, w1);
            const float* hp = h1s + k * H1P;
#pragma unroll
            for (int p = 0; p < 8; ++p) {
                float2 a = *(const float2*)(hp + 2 * p);
                acc0[p] = ffma2(a, w20, acc0[p]);
                acc1[p] = ffma2(a, w21, acc1[p]);
            }
        }
#pragma unroll
        for (int p = 0; p < 8; ++p) {
#pragma unroll
            for (int h = 0; h < 2; ++h) {
                size_t row = row0 + 2 * p + h;
                int b_ = (int)(row / Ln), t_ = (int)(row % Ln);
                float* fp = g_feat + ((size_t)t_ * Bn + b_) * F2;
                float v0 = h ? acc0[p].y : acc0[p].x;
                float v1 = h ? acc1[p].y : acc1[p].x;
                fp[tid] = fmaxf(v0, 0.f);
                fp[tid + 256] = fmaxf(v1, 0.f);
            }
        }
    }
}

// ---- xg GEMM (unchanged) ----
template <int K, bool SRC_KMAJOR>
__global__ __launch_bounds__(256, 1) void xg2_kernel(const float* __restrict__ A,
                                                     const float* __restrict__ W4,
                                                     const float* __restrict__ bsum,
                                                     float* __restrict__ out) {
    extern __shared__ float As[];  // [K][36]
    const int tid = threadIdx.x;
    const int row0 = blockIdx.x * 32;

    if (SRC_KMAJOR) {
        const int t = row0 >> 7, b0 = row0 & 127;
        const float* base = A + ((size_t)t * K) * 128 + b0;
        for (int i = tid; i < K * 8; i += 256) {
            int k = i >> 3, r4 = (i & 7) * 4;
            *(float4*)(As + k * 36 + r4) = *(const float4*)(base + (size_t)k * 128 + r4);
        }
    } else {
        constexpr int KQ = K / 4;
        for (int i = tid; i < 32 * KQ; i += 256) {
            int r = i / KQ, kq = i % KQ;
            float4 v = *(const float4*)(A + (size_t)(row0 + r) * K + kq * 4);
            As[(kq * 4 + 0) * 36 + r] = v.x;
            As[(kq * 4 + 1) * 36 + r] = v.y;
            As[(kq * 4 + 2) * 36 + r] = v.z;
            As[(kq * 4 + 3) * 36 + r] = v.w;
        }
    }
    __syncthreads();

    float2 acc[16][4];
#pragma unroll
    for (int p = 0; p < 16; ++p)
#pragma unroll
        for (int g = 0; g < 4; ++g) acc[p][g] = make_float2(0.f, 0.f);

    const float4* wp = (const float4*)W4 + tid;
#pragma unroll 2
    for (int k = 0; k < K; ++k) {
        float4 w4 = wp[(size_t)k * 256];
        float2 w2[4];
        w2[0] = make_float2(w4.x, w4.x);
        w2[1] = make_float2(w4.y, w4.y);
        w2[2] = make_float2(w4.z, w4.z);
        w2[3] = make_float2(w4.w, w4.w);
        const float4* ap = (const float4*)(As + k * 36);
#pragma unroll
        for (int q = 0; q < 8; ++q) {
            float4 a4 = ap[q];
            float2 alo = make_float2(a4.x, a4.y);
            float2 ahi = make_float2(a4.z, a4.w);
#pragma unroll
            for (int g = 0; g < 4; ++g) {
                acc[2 * q][g]     = ffma2(alo, w2[g], acc[2 * q][g]);
                acc[2 * q + 1][g] = ffma2(ahi, w2[g], acc[2 * q + 1][g]);
            }
        }
    }

    float bb[4];
#pragma unroll
    for (int g = 0; g < 4; ++g) bb[g] = bsum[tid + g * 256];
#pragma unroll
    for (int p = 0; p < 16; ++p) {
        float* o0 = out + (size_t)(row0 + 2 * p) * G4 + tid;
        float* o1 = o0 + G4;
#pragma unroll
        for (int g = 0; g < 4; ++g) {
            o0[g * 256] = acc[p][g].x + bb[g];
            o1[g * 256] = acc[p][g].y + bb[g];
        }
    }
}

// ---- LSTM recurrence (lstm3 layout, fast activations, per-layer state) ----
template <bool OUT_TBU>
__global__ __launch_bounds__(256) void lstm3_kernel(const float* __restrict__ xg,
                                                    const float* __restrict__ w_hh,
                                                    float* __restrict__ hout,
                                                    unsigned* __restrict__ ctrbase,
                                                    int layer) {
    extern __shared__ float sm[];
    float* w_s = sm;                        // [32 cols][260]
    float* h_s = sm + 32 * WPITCH;          // [256 k][32 rows]
    float* gx  = sm + 32 * WPITCH + Hn * 32; // [32 cols][36]

    const int tid = threadIdx.x;
    const int bid = blockIdx.x;
    const int ubase = (bid & 31) * 8;
    const int rbase = (bid >> 5) * 32;
    const int grp = bid >> 5;

    const int w = tid >> 5;
    const int lane = tid & 31;
    const int rq = lane >> 3;
    const int c = (w >> 1) * 8 + (lane & 7);
    const int r0 = (w & 1) * 16 + rq * 4;
    const int jcol = (c >> 3) * Hn + ubase + (c & 7);

    for (int i = tid; i < 32 * Hn; i += 256) {
        int cc = i >> 8, k = i & 255;
        int jc = (cc >> 3) * Hn + ubase + (cc & 7);
        w_s[cc * WPITCH + k] = w_hh[(size_t)jc * Hn + k];
    }

    const int pu = tid >> 5;
    const int pr = tid & 31;
    float cst = 0.f;
    unsigned* ctr = ctrbase + grp * 32;

    const float* xbase = xg + ((size_t)rbase + r0) * G4 + jcol;
    float x0 = xbase[0];
    float x1 = xbase[G4];
    float x2 = xbase[2 * G4];
    float x3 = xbase[3 * G4];

    __syncthreads();

    for (int t = 0; t < Ln; ++t) {
        const float* hrd = g_hstate[layer][t & 1];
        float* hwr = g_hstate[layer][(t + 1) & 1];

        for (int i = tid; i < Hn * 8; i += 256) {
            int k = i >> 3, r4 = (i & 7) * 4;
            *(float4*)(h_s + k * 32 + r4) = *(const float4*)(hrd + k * Bn + rbase + r4);
        }
        __syncthreads();

        float2 a01 = make_float2(0.f, 0.f);
        float2 a23 = make_float2(0.f, 0.f);
        const float* hp = h_s + r0;
        const float* wp = w_s + c * WPITCH;
#pragma unroll 4
        for (int k = 0; k < Hn; k += 4) {
            float4 wv = *(const float4*)(wp + k);
            float4 h0 = *(const float4*)(hp + (k + 0) * 32);
            a01 = ffma2(make_float2(h0.x, h0.y), make_float2(wv.x, wv.x), a01);
            a23 = ffma2(make_float2(h0.z, h0.w), make_float2(wv.x, wv.x), a23);
            float4 h1 = *(const float4*)(hp + (k + 1) * 32);
            a01 = ffma2(make_float2(h1.x, h1.y), make_float2(wv.y, wv.y), a01);
            a23 = ffma2(make_float2(h1.z, h1.w), make_float2(wv.y, wv.y), a23);
            float4 h2 = *(const float4*)(hp + (k + 2) * 32);
            a01 = ffma2(make_float2(h2.x, h2.y), make_float2(wv.z, wv.z), a01);
            a23 = ffma2(make_float2(h2.z, h2.w), make_float2(wv.z, wv.z), a23);
            float4 h3 = *(const float4*)(hp + (k + 3) * 32);
            a01 = ffma2(make_float2(h3.x, h3.y), make_float2(wv.w, wv.w), a01);
            a23 = ffma2(make_float2(h3.z, h3.w), make_float2(wv.w, wv.w), a23);
        }
        a01.x += x0; a01.y += x1; a23.x += x2; a23.y += x3;
        *(float4*)(gx + c * 36 + r0) = make_float4(a01.x, a01.y, a23.x, a23.y);
        __syncthreads();

        float iv = gx[(0 * 8 + pu) * 36 + pr];
        float fv = gx[(1 * 8 + pu) * 36 + pr];
        float gv = gx[(2 * 8 + pu) * 36 + pr];
        float ov = gx[(3 * 8 + pu) * 36 + pr];
        iv = fast_sigmoid(iv);
        fv = fast_sigmoid(fv);
        gv = fast_tanh(gv);
        ov = fast_sigmoid(ov);
        cst = fv * cst + iv * gv;
        float hv = ov * fast_tanh(cst);
        hwr[(ubase + pu) * Bn + rbase + pr] = hv;
        if (OUT_TBU)
            hout[((size_t)t * Bn + rbase + pr) * Hn + ubase + pu] = hv;
        else
            hout[((size_t)t * Hn + ubase + pu) * Bn + rbase + pr] = hv;

        if (t + 1 < Ln) {
            const float* xp = xg + (((size_t)(t + 1)) * Bn + rbase + r0) * G4 + jcol;
            x0 = xp[0];
            x1 = xp[G4];
            x2 = xp[2 * G4];
            x3 = xp[3 * G4];
        }

        __syncthreads();
        if (tid == 0) {
            asm volatile("red.release.gpu.global.add.u32 [%0], %1;" :: "l"(ctr), "r"(1u) : "memory");
            const unsigned target = (unsigned)(t + 1) * 32u;
            unsigned v;
            do {
                asm volatile("ld.acquire.gpu.global.u32 %0, [%1];" : "=r"(v) : "l"(ctr) : "memory");
            } while (v < target);
        }
        __syncthreads();
    }
}

// ---- decision head + ragged mean ----
__global__ __launch_bounds__(256) void decision_kernel(const float* __restrict__ hseq,
                                                       const float* __restrict__ Wd,
                                                       const float* __restrict__ bd,
                                                       const int* __restrict__ length,
                                                       float* __restrict__ out) {
    const int b = blockIdx.x;
    const int tid = threadIdx.x;
    const int len = length[b];
    const float w = Wd[tid];
    float s0 = 0.f, s1 = 0.f, s2 = 0.f, s3 = 0.f;
    int t = 0;
    for (; t + 4 <= len; t += 4) {
        s0 = fmaf(hseq[((size_t)(t + 0) * Bn + b) * Hn + tid], w, s0);
        s1 = fmaf(hseq[((size_t)(t + 1) * Bn + b) * Hn + tid], w, s1);
        s2 = fmaf(hseq[((size_t)(t + 2) * Bn + b) * Hn + tid], w, s2);
        s3 = fmaf(hseq[((size_t)(t + 3) * Bn + b) * Hn + tid], w, s3);
    }
    for (; t < len; ++t) s0 = fmaf(hseq[((size_t)t * Bn + b) * Hn + tid], w, s0);
    float s = (s0 + s1) + (s2 + s3);
    __shared__ float red[256];
    red[tid] = s;
    __syncthreads();
    for (int st = 128; st > 0; st >>= 1) {
        if (tid < st) red[tid] += red[tid + st];
        __syncthreads();
    }
    if (tid == 0) out[b] = red[0] / (float)len + bd[0];
}

extern "C" void kernel_launch(void* const* d_in, const int* in_sizes, int n_in,
                              void* d_out, int out_size) {
    const float* x     = (const float*)d_in[0];
    const int* length  = (const int*)d_in[1];
    const float* W1    = (const float*)d_in[2];
    const float* b1    = (const float*)d_in[3];
    const float* W2    = (const float*)d_in[4];
    const float* b2    = (const float*)d_in[5];
    const float* w_ih0 = (const float*)d_in[6];
    const float* w_hh0 = (const float*)d_in[7];
    const float* b_ih0 = (const float*)d_in[8];
    const float* b_hh0 = (const float*)d_in[9];
    const float* w_ih1 = (const float*)d_in[10];
    const float* w_hh1 = (const float*)d_in[11];
    const float* b_ih1 = (const float*)d_in[12];
    const float* b_hh1 = (const float*)d_in[13];
    const float* w_ih2 = (const float*)d_in[14];
    const float* w_hh2 = (const float*)d_in[15];
    const float* b_ih2 = (const float*)d_in[16];
    const float* b_hh2 = (const float*)d_in[17];
    const float* Wd    = (const float*)d_in[18];
    const float* bd    = (const float*)d_in[19];
    float* out = (float*)d_out;

    float *dP0, *dP1, *dP2, *dB0, *dB1, *dB2, *dFeat, *dXg, *dHA, *dHB;
    unsigned* dCtr;
    cudaGetSymbolAddress((void**)&dP0, g_W4_0);
    cudaGetSymbolAddress((void**)&dP1, g_W4_1);
    cudaGetSymbolAddress((void**)&dP2, g_W4_2);
    cudaGetSymbolAddress((void**)&dB0, g_bsum0);
    cudaGetSymbolAddress((void**)&dB1, g_bsum1);
    cudaGetSymbolAddress((void**)&dB2, g_bsum2);
    cudaGetSymbolAddress((void**)&dFeat, g_feat);
    cudaGetSymbolAddress((void**)&dXg, g_xg);
    cudaGetSymbolAddress((void**)&dHA, g_hA);
    cudaGetSymbolAddress((void**)&dHB, g_hB);
    cudaGetSymbolAddress((void**)&dCtr, g_grpctr);

    const int xg_smem512 = 512 * 36 * sizeof(float);
    const int xg_smem256 = 256 * 36 * sizeof(float);
    const int lstm_smem = (32 * WPITCH + Hn * 32 + 32 * 36) * sizeof(float);
    cudaFuncSetAttribute(xg2_kernel<F2, false>, cudaFuncAttributeMaxDynamicSharedMemorySize, xg_smem512);
    cudaFuncSetAttribute(xg2_kernel<Hn, true>, cudaFuncAttributeMaxDynamicSharedMemorySize, xg_smem256);
    cudaFuncSetAttribute(lstm3_kernel<false>, cudaFuncAttributeMaxDynamicSharedMemorySize, lstm_smem);
    cudaFuncSetAttribute(lstm3_kernel<true>, cudaFuncAttributeMaxDynamicSharedMemorySize, lstm_smem);

    prep_kernel<<<(PREP_TOTAL + 255) / 256, 256>>>(W1, W2, w_ih0, w_ih1, w_ih2,
                                                   b_ih0, b_hh0, b_ih1, b_hh1, b_ih2, b_hh2);

    const int nrows = Bn * Ln;
    mlp2_kernel<<<nrows / 16, 256>>>(x, b1, b2);

    // layer 0  (lstm3 is the 4th launch -> gets profiled by ncu)
    xg2_kernel<F2, false><<<nrows / 32, 256, xg_smem512>>>(dFeat, dP0, dB0, dXg);
    lstm3_kernel<false><<<128, 256, lstm_smem>>>(dXg, w_hh0, dHA, dCtr + 0 * 128, 0);
    // layer 1
    xg2_kernel<Hn, true><<<nrows / 32, 256, xg_smem256>>>(dHA, dP1, dB1, dXg);
    lstm3_kernel<false><<<128, 256, lstm_smem>>>(dXg, w_hh1, dHB, dCtr + 1 * 128, 1);
    // layer 2
    xg2_kernel<Hn, true><<<nrows / 32, 256, xg_smem256>>>(dHB, dP2, dB2, dXg);
    lstm3_kernel<true><<<128, 256, lstm_smem>>>(dXg, w_hh2, dHA, dCtr + 2 * 128, 2);

    decision_kernel<<<Bn, 256>>>(dHA, Wd, bd, length, out);
}